// round 5
// baseline (speedup 1.0000x reference)
#include <cuda_runtime.h>
#include <math.h>

// RBFSolver: out[0,f,t] = sum_k w_k / (1 + 4pi^2 ex^2)
//            out[1,f,t] = -2pi sum_k w_k ex / (1 + 4pi^2 ex^2)
// ex = exp(log f + log t + y_k), y = linspace(-50,50,500), w_k = exp(-y_k^2)*dy.
//
// Structural optimization: the result depends on (f,t) ONLY through
// s = log f + log t.  Both outputs are smooth O(1)-scale functions of s
// (Gaussian-smoothed logistic / sech).  So we:
//   * precompute (a_re(s), a_im(s)) on the HOST with the exact 500-point
//     quadrature in double precision, on a grid s in [-14, 6], h = 1/16;
//   * fit an exact 4-point Lagrange cubic per cell (error <= ~5e-6 abs,
//     tolerance is 1e-3);
//   * pass the 10KB coefficient table by value (constant bank), stage it
//     into shared memory, and evaluate 2 Horner cubics per element.
// Per-thread work: 1 log, 1 add, 1 gather, 6 FMA — no loop, no rcp, no exp.

#define F_DIM   512
#define T_DIM   256

#define S0_D    (-14.0)
#define H_D     (0.0625)        // 1/16
#define NCELLS  320             // covers s in [-14, 6]

struct TblParam {
    // c[2*i]   = (c0,c1,c2,c3) for a_re on cell i
    // c[2*i+1] = (c0,c1,c2,c3) for a_im on cell i
    float4 c[2 * NCELLS];       // 10240 bytes
};

__global__ __launch_bounds__(T_DIM)
void rbf_solver_kernel(const float* __restrict__ f_vec,
                       const float* __restrict__ log_t_vec,
                       float* __restrict__ out,
                       const TblParam tbl)
{
    __shared__ float4 sh[2 * NCELLS];

    // Stage coefficient table: constant bank -> shared (3 rounds of 256).
    #pragma unroll
    for (int j = threadIdx.x; j < 2 * NCELLS; j += T_DIM)
        sh[j] = tbl.c[j];
    __syncthreads();

    const int f = blockIdx.x;     // 0..511
    const int t = threadIdx.x;    // 0..255

    const float s = __logf(f_vec[f]) + log_t_vec[t];

    float x = (s - (float)S0_D) * 16.0f;            // cell coordinate
    x = fminf(fmaxf(x, 0.0f), (float)NCELLS - 0.001f);
    const int   i = (int)x;                          // 0..NCELLS-1
    const float u = x - (float)i;                    // [0,1)

    const float4 cr = sh[2 * i];                     // LDS.128 gather
    const float4 ci = sh[2 * i + 1];

    const float re = fmaf(fmaf(fmaf(cr.w, u, cr.z), u, cr.y), u, cr.x);
    const float im = fmaf(fmaf(fmaf(ci.w, u, ci.z), u, ci.y), u, ci.x);

    const int idx = f * T_DIM + t;
    out[idx]                 = re;
    out[F_DIM * T_DIM + idx] = im;
}

extern "C" void kernel_launch(void* const* d_in, const int* in_sizes, int n_in,
                              void* d_out, int out_size)
{
    const float* f_vec     = (const float*)d_in[0];   // (512,)
    const float* log_t_vec = (const float*)d_in[1];   // (256,)
    float* out             = (float*)d_out;           // (2, 512, 256)

    (void)in_sizes; (void)n_in; (void)out_size;

    // ---- Host: input-independent table (runs at capture time only) ----
    static const double PI      = 3.14159265358979323846;
    const double PI4SQ  = 4.0 * PI * PI;
    const double TWO_PI = 2.0 * PI;
    const double dy     = 100.0 / 499.0;

    // Nodes j = -1 .. NCELLS+2  (stored at index j+1), s_j = S0 + j*h.
    static double Gre[NCELLS + 4];
    static double Gim[NCELLS + 4];
    for (int jj = 0; jj < NCELLS + 4; ++jj) {
        const double s = S0_D + (double)(jj - 1) * H_D;
        double gre = 0.0, gim = 0.0;
        for (int k = 0; k < 500; ++k) {
            const double y  = -50.0 + (double)k * dy;
            const double w  = exp(-y * y) * dy;
            if (w == 0.0) continue;
            const double e  = exp(s + y);
            const double d  = 1.0 + PI4SQ * e * e;
            gre += w / d;
            gim += w * e / d;
        }
        Gre[jj] = gre;
        Gim[jj] = -TWO_PI * gim;
    }

    // Exact 4-point Lagrange cubic per cell in local u = (s - s_i)/h:
    //   p(u) = f0 + c1 u + c2 u^2 + c3 u^3, through f(-1),f(0),f(1),f(2).
    TblParam tbl;
    for (int i = 0; i < NCELLS; ++i) {
        const double* G[2] = { Gre, Gim };
        for (int q = 0; q < 2; ++q) {
            const double fm1 = G[q][i];        // node i-1 (stored at i)
            const double f0  = G[q][i + 1];
            const double f1  = G[q][i + 2];
            const double f2  = G[q][i + 3];
            const double c1 = -fm1 / 3.0 - f0 / 2.0 + f1 - f2 / 6.0;
            const double c2 =  fm1 / 2.0 - f0 + f1 / 2.0;
            const double c3 = -fm1 / 6.0 + f0 / 2.0 - f1 / 2.0 + f2 / 6.0;
            tbl.c[2 * i + q] = make_float4((float)f0, (float)c1,
                                           (float)c2, (float)c3);
        }
    }

    rbf_solver_kernel<<<F_DIM, T_DIM>>>(f_vec, log_t_vec, out, tbl);
}

// round 6
// speedup vs baseline: 2.2185x; 2.2185x over previous
#include <cuda_runtime.h>
#include <math.h>

// RBFSolver: out[0,f,t] = sum_k w_k / (1 + 4pi^2 ex^2)
//            out[1,f,t] = -2pi sum_k w_k ex / (1 + 4pi^2 ex^2)
// ex = exp(log f + log t + y_k), y = linspace(-50,50,500), w_k = exp(-y_k^2)*dy.
//
// Structure: the result depends on (f,t) only through s = log f + log t, and
// both outputs are smooth O(1)-scale functions of s. Two-kernel graph:
//   1) init: 324-node table of (a_re(s), a_im(s)) on s in [-14,6], h=1/16,
//      computed on-device with the 70-point truncated quadrature (fp32,
//      shared (E,w) table, batched like the direct kernel). ~1us.
//   2) main: per (f,t): 1 log, 4 scattered LDG.64 node gathers (table is
//      L1/L2 resident), exact 4-point Lagrange cubic, packed f32x2 accum.
// R5 lesson: NEVER dynamically index a by-value param (divergent LDC
// serializes on the half-rate constant port). Global + L1 handles
// divergence natively.

#define F_DIM   512
#define T_DIM   256

#define NY_K0   215
#define NY_N    70          // |y| <= 6.92; weights below 2e-22 outside

#define S0      (-14.0f)
#define INVH    16.0f
#define NCELLS  320
#define N_NODES (NCELLS + 4)    // node j at index j+1, j = -1..NCELLS+2

typedef unsigned long long u64;

#define FMA2(o,a,b,c) asm("fma.rn.f32x2 %0, %1, %2, %3;" : "=l"(o) : "l"(a), "l"(b), "l"(c))
#define MUL2(o,a,b)   asm("mul.rn.f32x2 %0, %1, %2;"     : "=l"(o) : "l"(a), "l"(b))
#define PACK2(o,lo,hi)   asm("mov.b64 %0, {%1, %2};" : "=l"(o) : "f"(lo), "f"(hi))
#define UNPACK2(lo,hi,i) asm("mov.b64 {%0, %1}, %2;" : "=f"(lo), "=f"(hi) : "l"(i))

// Node table: (a_re, a_im) per node, read as u64 for packed f32x2 math.
__device__ u64 g_nodes[N_NODES];

// ---------------------------------------------------------------------------
// Kernel 1: build the 324-node table. grid 3 x 128.
// ---------------------------------------------------------------------------
__global__ __launch_bounds__(128)
void rbf_init_kernel()
{
    __shared__ float2 ew[NY_N];     // (exp(y_k), w_k)

    const float dy = 100.0f / 499.0f;

    for (int j = threadIdx.x; j < NY_N; j += 128) {
        float y = fmaf((float)(NY_K0 + j), dy, -50.0f);
        ew[j] = make_float2(__expf(y), __expf(-y * y) * dy);
    }
    __syncthreads();

    const int node = blockIdx.x * 128 + threadIdx.x;
    if (node >= N_NODES) return;

    // s_j = S0 + (node - 1) * h
    const float s   = fmaf((float)(node - 1), 1.0f / INVH, S0);
    const float esc = __expf(s) * 6.283185307179586f;    // 2pi * exp(s)

    // two independent accumulator streams to shorten the chain
    float re0 = 0.f, re1 = 0.f, im0 = 0.f, im1 = 0.f;
    #pragma unroll
    for (int k = 0; k < NY_N; k += 2) {
        float2 v0 = ew[k], v1 = ew[k + 1];
        float exF0 = esc * v0.x;
        float exF1 = esc * v1.x;
        float d0 = fmaf(exF0, exF0, 1.0f);
        float d1 = fmaf(exF1, exF1, 1.0f);
        float tw0 = __fdividef(v0.y, d0);
        float tw1 = __fdividef(v1.y, d1);
        re0 += tw0;             re1 += tw1;
        im0 = fmaf(tw0, exF0, im0);
        im1 = fmaf(tw1, exF1, im1);
    }

    u64 packed;
    PACK2(packed, re0 + re1, -(im0 + im1));   // (a_re, a_im)
    g_nodes[node] = packed;
}

// ---------------------------------------------------------------------------
// Kernel 2: evaluate via exact 4-point Lagrange cubic. grid 512 x 256.
// ---------------------------------------------------------------------------
__global__ __launch_bounds__(T_DIM)
void rbf_eval_kernel(const float* __restrict__ f_vec,
                     const float* __restrict__ log_t_vec,
                     float* __restrict__ out)
{
    const int f = blockIdx.x;     // 0..511
    const int t = threadIdx.x;    // 0..255

    const float s = __logf(f_vec[f]) + log_t_vec[t];

    float x = (s - S0) * INVH;
    x = fminf(fmaxf(x, 0.0f), (float)NCELLS - 0.001f);
    const int   i = (int)x;                 // cell 0..NCELLS-1
    const float u = x - (float)i;           // [0,1)

    // nodes (i-1, i, i+1, i+2) live at g_nodes[i .. i+3]
    const u64 n0 = g_nodes[i];
    const u64 n1 = g_nodes[i + 1];
    const u64 n2 = g_nodes[i + 2];
    const u64 n3 = g_nodes[i + 3];

    // Lagrange weights through 4 equispaced nodes
    const float a = u + 1.0f, b = u, c = u - 1.0f, d = u - 2.0f;
    const float ad = a * d, bc = b * c;
    const float w0 = -bc * d * (1.0f / 6.0f);
    const float w1 =  ad * c * 0.5f;
    const float w2 = -ad * b * 0.5f;
    const float w3 =  a * bc * (1.0f / 6.0f);

    u64 w02, w12, w22, w32, acc;
    PACK2(w02, w0, w0);
    PACK2(w12, w1, w1);
    PACK2(w22, w2, w2);
    PACK2(w32, w3, w3);

    MUL2(acc, w02, n0);
    FMA2(acc, w12, n1, acc);
    FMA2(acc, w22, n2, acc);
    FMA2(acc, w32, n3, acc);

    float re, im;
    UNPACK2(re, im, acc);

    const int idx = f * T_DIM + t;
    out[idx]                 = re;
    out[F_DIM * T_DIM + idx] = im;
}

extern "C" void kernel_launch(void* const* d_in, const int* in_sizes, int n_in,
                              void* d_out, int out_size)
{
    const float* f_vec     = (const float*)d_in[0];   // (512,)
    const float* log_t_vec = (const float*)d_in[1];   // (256,)
    float* out             = (float*)d_out;           // (2, 512, 256)

    (void)in_sizes; (void)n_in; (void)out_size;

    rbf_init_kernel<<<3, 128>>>();
    rbf_eval_kernel<<<F_DIM, T_DIM>>>(f_vec, log_t_vec, out);
}

// round 7
// speedup vs baseline: 2.7604x; 1.2442x over previous
#include <cuda_runtime.h>
#include <math.h>

// RBFSolver: out[0,f,t] = sum_k w_k / (1 + 4pi^2 ex^2)
//            out[1,f,t] = -2pi sum_k w_k ex / (1 + 4pi^2 ex^2)
// ex = exp(log f + log t + y_k), y = linspace(-50,50,500), w_k = exp(-y_k^2)*dy.
//
// Structure: the result depends on (f,t) only through s = log f + log t, and
// both outputs are smooth O(1)-scale functions of s. Two-kernel graph:
//   1) init: 324-node table of (a_re(s), a_im(s)) on s in [-14,6], h=1/16,
//      44-point truncated quadrature (|y|<=4.5; validated rel_err ~2.7e-6).
//   2) eval: stage the 2.6KB table into SHARED (coalesced), then per (f,t):
//      1 log, 4 divergent LDS.64 gathers (smem crossbar eats the divergence
//      at ~2-4 cyc, vs L1tex per-line replay chains for divergent LDG),
//      exact 4-point Lagrange cubic, packed f32x2 accumulation.
// R5 lesson: never dynamically index a by-value param (const-port serialize).
// R6 lesson: divergent table gathers must hit smem, not gmem.

#define F_DIM   512
#define T_DIM   256

#define NY_K0   227
#define NY_N    44          // |y| <= 4.5

#define S0      (-14.0f)
#define INVH    16.0f
#define NCELLS  320
#define N_NODES (NCELLS + 4)    // node j at index j+1, j = -1..NCELLS+2

typedef unsigned long long u64;

#define FMA2(o,a,b,c) asm("fma.rn.f32x2 %0, %1, %2, %3;" : "=l"(o) : "l"(a), "l"(b), "l"(c))
#define MUL2(o,a,b)   asm("mul.rn.f32x2 %0, %1, %2;"     : "=l"(o) : "l"(a), "l"(b))
#define PACK2(o,lo,hi)   asm("mov.b64 %0, {%1, %2};" : "=l"(o) : "f"(lo), "f"(hi))
#define UNPACK2(lo,hi,i) asm("mov.b64 {%0, %1}, %2;" : "=f"(lo), "=f"(hi) : "l"(i))

// Node table: (a_re, a_im) per node, as u64 for packed f32x2 math.
__device__ u64 g_nodes[N_NODES];

// ---------------------------------------------------------------------------
// Kernel 1: build the 324-node table. grid 3 x 128.
// ---------------------------------------------------------------------------
__global__ __launch_bounds__(128)
void rbf_init_kernel()
{
    __shared__ float2 ew[NY_N];     // (exp(y_k), w_k)

    const float dy = 100.0f / 499.0f;

    if (threadIdx.x < NY_N) {
        float y = fmaf((float)(NY_K0 + (int)threadIdx.x), dy, -50.0f);
        ew[threadIdx.x] = make_float2(__expf(y), __expf(-y * y) * dy);
    }
    __syncthreads();

    const int node = blockIdx.x * 128 + threadIdx.x;
    if (node >= N_NODES) return;

    // s_j = S0 + (node - 1) * h
    const float s   = fmaf((float)(node - 1), 1.0f / INVH, S0);
    const float esc = __expf(s) * 6.283185307179586f;    // 2pi * exp(s)

    float re0 = 0.f, re1 = 0.f, im0 = 0.f, im1 = 0.f;
    #pragma unroll
    for (int k = 0; k < NY_N; k += 2) {
        float2 v0 = ew[k], v1 = ew[k + 1];
        float exF0 = esc * v0.x;
        float exF1 = esc * v1.x;
        float d0 = fmaf(exF0, exF0, 1.0f);
        float d1 = fmaf(exF1, exF1, 1.0f);
        float tw0 = __fdividef(v0.y, d0);
        float tw1 = __fdividef(v1.y, d1);
        re0 += tw0;             re1 += tw1;
        im0 = fmaf(tw0, exF0, im0);
        im1 = fmaf(tw1, exF1, im1);
    }

    u64 packed;
    PACK2(packed, re0 + re1, -(im0 + im1));   // (a_re, a_im)
    g_nodes[node] = packed;
}

// ---------------------------------------------------------------------------
// Kernel 2: stage table to shared, evaluate 4-pt Lagrange cubic. grid 512x256.
// ---------------------------------------------------------------------------
__global__ __launch_bounds__(T_DIM)
void rbf_eval_kernel(const float* __restrict__ f_vec,
                     const float* __restrict__ log_t_vec,
                     float* __restrict__ out)
{
    __shared__ u64 sh[N_NODES];

    // Coalesced bulk stage: 2 rounds of 256 LDG.64.
    #pragma unroll
    for (int j = threadIdx.x; j < N_NODES; j += T_DIM)
        sh[j] = g_nodes[j];

    const int f = blockIdx.x;     // 0..511
    const int t = threadIdx.x;    // 0..255

    const float s = __logf(f_vec[f]) + log_t_vec[t];

    float x = (s - S0) * INVH;
    x = fminf(fmaxf(x, 0.0f), (float)NCELLS - 0.001f);
    const int   i = (int)x;                 // cell 0..NCELLS-1
    const float u = x - (float)i;           // [0,1)

    __syncthreads();

    // nodes (i-1, i, i+1, i+2) live at sh[i .. i+3]  (divergent LDS.64)
    const u64 n0 = sh[i];
    const u64 n1 = sh[i + 1];
    const u64 n2 = sh[i + 2];
    const u64 n3 = sh[i + 3];

    // Lagrange weights through 4 equispaced nodes
    const float a = u + 1.0f, b = u, c = u - 1.0f, d = u - 2.0f;
    const float ad = a * d, bc = b * c;
    const float w0 = -bc * d * (1.0f / 6.0f);
    const float w1 =  ad * c * 0.5f;
    const float w2 = -ad * b * 0.5f;
    const float w3 =  a * bc * (1.0f / 6.0f);

    u64 w02, w12, w22, w32, acc;
    PACK2(w02, w0, w0);
    PACK2(w12, w1, w1);
    PACK2(w22, w2, w2);
    PACK2(w32, w3, w3);

    MUL2(acc, w02, n0);
    FMA2(acc, w12, n1, acc);
    FMA2(acc, w22, n2, acc);
    FMA2(acc, w32, n3, acc);

    float re, im;
    UNPACK2(re, im, acc);

    const int idx = f * T_DIM + t;
    out[idx]                 = re;
    out[F_DIM * T_DIM + idx] = im;
}

extern "C" void kernel_launch(void* const* d_in, const int* in_sizes, int n_in,
                              void* d_out, int out_size)
{
    const float* f_vec     = (const float*)d_in[0];   // (512,)
    const float* log_t_vec = (const float*)d_in[1];   // (256,)
    float* out             = (float*)d_out;           // (2, 512, 256)

    (void)in_sizes; (void)n_in; (void)out_size;

    rbf_init_kernel<<<3, 128>>>();
    rbf_eval_kernel<<<F_DIM, T_DIM>>>(f_vec, log_t_vec, out);
}

// round 8
// speedup vs baseline: 2.7860x; 1.0093x over previous
#include <cuda_runtime.h>
#include <math.h>

// RBFSolver: out[0,f,t] = sum_k w_k / (1 + 4pi^2 ex^2)
//            out[1,f,t] = -2pi sum_k w_k ex / (1 + 4pi^2 ex^2)
// ex = exp(log f + log t + y_k), y = linspace(-50,50,500), w_k = exp(-y_k^2)*dy.
//
// The reference's Riemann sum (h ~ 0.2, analytic Gaussian-weighted integrand)
// equals the true integral  int e^{-y^2} g(s+y) dy  to ~1e-21 relative
// (trapezoid rule is exponentially accurate here). g is analytic in the strip
// |Im y| < pi/2, so 16-point GAUSS-HERMITE reproduces it to ~2e-7 relative:
// the 44-point truncated grid sum becomes 16 points -> 8 packed f32x2 pairs.
//
// Other carried optimizations (validated R2-R4):
//  * exp(log f + log t) = f * exp(log t): no log.
//  * exF = 2pi*ex folds the final 2pi into the accumulation exactly.
//  * GH (E_i = e^{x_i}, w_i) table: host-computed (double), passed by value,
//    accessed ONLY at compile-time indices (uniform const-bank reads; R5
//    showed divergent LDC is fatal, uniform is free).
//  * Batched reciprocal: 1 MUFU.RCP per packed pair.
//  * Single launch (R6/R7 showed a ~4.5us per-launch floor dominates).

#define GH_N    16
#define GH_PAIR 8
#define F_DIM   512
#define T_DIM   256

typedef unsigned long long u64;

#define MUL2(o,a,b)   asm("mul.rn.f32x2 %0, %1, %2;"     : "=l"(o) : "l"(a), "l"(b))
#define ADD2(o,a,b)   asm("add.rn.f32x2 %0, %1, %2;"     : "=l"(o) : "l"(a), "l"(b))
#define FMA2(o,a,b,c) asm("fma.rn.f32x2 %0, %1, %2, %3;" : "=l"(o) : "l"(a), "l"(b), "l"(c))
#define PACK2(o,lo,hi)   asm("mov.b64 %0, {%1, %2};" : "=l"(o) : "f"(lo), "f"(hi))
#define UNPACK2(lo,hi,i) asm("mov.b64 {%0, %1}, %2;" : "=f"(lo), "=f"(hi) : "l"(i))
#define RCPA(o,a)     asm("rcp.approx.ftz.f32 %0, %1;" : "=f"(o) : "f"(a))

struct QuadTbl {
    // p[i] = (E_2i, E_2i+1, w_2i, w_2i+1); E = exp(node), w = GH weight
    float4 p[GH_PAIR];
};

__global__ __launch_bounds__(T_DIM, 4)
void rbf_solver_kernel(const float* __restrict__ f_vec,
                       const float* __restrict__ log_t_vec,
                       float* __restrict__ out,
                       const QuadTbl tbl)
{
    const int f = blockIdx.x;     // 0..511
    const int t = threadIdx.x;    // 0..255

    // esc = 2pi * exp(log f + log t) = 2pi * f * exp(log t)
    const float esc = 6.283185307179586f * f_vec[f] * __expf(log_t_vec[t]);

    u64 esc2, one2, re2, im2;
    PACK2(esc2, esc, esc);
    {
        float one = 1.0f, zero = 0.0f;
        PACK2(one2, one, one);
        PACK2(re2, zero, zero);
        PACK2(im2, zero, zero);
    }

    #pragma unroll
    for (int i = 0; i < GH_PAIR; ++i) {
        float4 v = tbl.p[i];                 // uniform const-bank read
        u64 E2, w2;
        PACK2(E2, v.x, v.y);
        PACK2(w2, v.z, v.w);

        u64 exF2;  MUL2(exF2, esc2, E2);            // 2pi*ex (x2)
        u64 d2;    FMA2(d2, exF2, exF2, one2);      // 1 + (2pi ex)^2 (x2)

        // Batched reciprocal: one MUFU for the pair. d0*d1 <= ~3e17, safe.
        float dlo, dhi;  UNPACK2(dlo, dhi, d2);
        float pr = dlo * dhi;
        float rr; RCPA(rr, pr);                     // MUFU.RCP (x1)
        float rlo = rr * dhi;
        float rhi = rr * dlo;
        u64 r2;    PACK2(r2, rlo, rhi);

        u64 tw2;   MUL2(tw2, w2, r2);               // w / denom (x2)
        ADD2(re2, re2, tw2);
        FMA2(im2, tw2, exF2, im2);                  // accumulates -a_im
    }

    float re_lo, re_hi, im_lo, im_hi;
    UNPACK2(re_lo, re_hi, re2);
    UNPACK2(im_lo, im_hi, im2);

    const int idx = f * T_DIM + t;
    out[idx]                 = re_lo + re_hi;       // a_re
    out[F_DIM * T_DIM + idx] = -(im_lo + im_hi);    // a_im
}

// ---------------------------------------------------------------------------
// Host: 16-point Gauss-Hermite nodes/weights (physicists' H_16), computed in
// double via sign-scan + bisection. Input-independent; runs at capture time.
// ---------------------------------------------------------------------------
static double hermite_H(int n, double x)
{
    double h0 = 1.0, h1 = 2.0 * x;
    for (int k = 1; k < n; ++k) {
        double h2 = 2.0 * x * h1 - 2.0 * (double)k * h0;
        h0 = h1; h1 = h2;
    }
    return h1;
}

extern "C" void kernel_launch(void* const* d_in, const int* in_sizes, int n_in,
                              void* d_out, int out_size)
{
    const float* f_vec     = (const float*)d_in[0];   // (512,)
    const float* log_t_vec = (const float*)d_in[1];   // (256,)
    float* out             = (float*)d_out;           // (2, 512, 256)

    (void)in_sizes; (void)n_in; (void)out_size;

    // Positive roots of H_16 by scan + bisection on (0, 6).
    double xr[GH_N];      // all 16 nodes, ascending
    double wt[GH_N];
    {
        double roots[8];
        int nr = 0;
        double step = 1e-3;
        double prev = hermite_H(GH_N, 1e-12);
        for (double x = step; x < 6.0 && nr < 8; x += step) {
            double cur = hermite_H(GH_N, x);
            if (prev * cur < 0.0) {
                double lo = x - step, hi = x;
                for (int it = 0; it < 80; ++it) {
                    double mid = 0.5 * (lo + hi);
                    double fm = hermite_H(GH_N, mid);
                    if (fm * prev <= 0.0) hi = mid; else lo = mid;
                }
                roots[nr++] = 0.5 * (lo + hi);
            }
            prev = cur;
        }
        // weights: w_i = 2^{n-1} n! sqrt(pi) / (n^2 * H_{n-1}(x_i)^2)
        double fact = 1.0;
        for (int k = 2; k <= GH_N; ++k) fact *= (double)k;
        const double wnum = ldexp(1.0, GH_N - 1) * fact * sqrt(3.14159265358979323846)
                            / ((double)GH_N * (double)GH_N);
        for (int i = 0; i < 8; ++i) {
            double hm = hermite_H(GH_N - 1, roots[i]);
            double w  = wnum / (hm * hm);
            // symmetric nodes +-x, same weight; ascending order
            xr[8 + i]     =  roots[i];
            xr[7 - i]     = -roots[i];
            wt[8 + i]     = w;
            wt[7 - i]     = w;
        }
    }

    QuadTbl tbl;
    for (int i = 0; i < GH_PAIR; ++i) {
        tbl.p[i] = make_float4((float)exp(xr[2 * i]), (float)exp(xr[2 * i + 1]),
                               (float)wt[2 * i],      (float)wt[2 * i + 1]);
    }

    rbf_solver_kernel<<<F_DIM, T_DIM>>>(f_vec, log_t_vec, out, tbl);
}